// round 10
// baseline (speedup 1.0000x reference)
#include <cuda_runtime.h>
#include <cuda_fp16.h>
#include <cstdint>
#include <math.h>

#define DO_   30
#define TPB   256

// ---------------- device scratch (no runtime alloc) ----------------
// x transformed to [b][d][h][w][cin] fp16
__device__ __align__(16) __half g_xt[16 * 32 * 32 * 32 * 16];
// weights [tap 27][cout 32][cin 16] fp16
__device__ __align__(16) __half g_w2[27 * 32 * 16];

// ---------------- helpers ----------------
__device__ __forceinline__ uint32_t smem_u32(const void* p) {
    uint32_t a;
    asm("{ .reg .u64 t; cvta.to.shared.u64 t, %1; cvt.u32.u64 %0, t; }" : "=r"(a) : "l"(p));
    return a;
}
__device__ __forceinline__ void cp_async16(uint32_t sdst, const void* gsrc) {
    asm volatile("cp.async.cg.shared.global [%0], [%1], 16;\n" :: "r"(sdst), "l"(gsrc));
}
__device__ __forceinline__ void cp_commit() { asm volatile("cp.async.commit_group;\n" ::: "memory"); }
template<int N> __device__ __forceinline__ void cp_wait() {
    asm volatile("cp.async.wait_group %0;\n" :: "n"(N) : "memory");
}
__device__ __forceinline__ void ldsm4(uint32_t* r, uint32_t addr) {
    asm volatile("ldmatrix.sync.aligned.m8n8.x4.shared.b16 {%0,%1,%2,%3}, [%4];"
        : "=r"(r[0]), "=r"(r[1]), "=r"(r[2]), "=r"(r[3]) : "r"(addr));
}
__device__ __forceinline__ void mma_f16(float* c, const uint32_t* a, const uint32_t* b) {
    asm volatile(
        "mma.sync.aligned.m16n8k16.row.col.f32.f16.f16.f32 "
        "{%0,%1,%2,%3}, {%4,%5,%6,%7}, {%8,%9}, {%0,%1,%2,%3};"
        : "+f"(c[0]), "+f"(c[1]), "+f"(c[2]), "+f"(c[3])
        : "r"(a[0]), "r"(a[1]), "r"(a[2]), "r"(a[3]), "r"(b[0]), "r"(b[1]));
}

// ---------------- merged transform kernel ----------------
__global__ __launch_bounds__(128) void xform_all(const float* __restrict__ x,
                                                 const float* __restrict__ w)
{
    const int t = threadIdx.x;
    if (blockIdx.x < 16384) {
        __shared__ float s[16][33];
        const int blk = blockIdx.x;            // (b*32 + d)*32 + h
        const int b = blk >> 10, d = (blk >> 5) & 31, h = blk & 31;

        const int cin = t >> 3, w4 = (t & 7) << 2;
        const float4 v = *(const float4*)(x + (((long)(b * 16 + cin) << 15) + (d << 10) + (h << 5) + w4));
        s[cin][w4 + 0] = v.x; s[cin][w4 + 1] = v.y; s[cin][w4 + 2] = v.z; s[cin][w4 + 3] = v.w;
        __syncthreads();

        const long ob = (long)blk * 512;
        #pragma unroll
        for (int j = 0; j < 4; ++j) {
            const int e = t + (j << 7);        // = w*16 + cin
            const int ww = e >> 4, c = e & 15;
            g_xt[ob + e] = __float2half_rn(s[c][ww]);
        }
    } else {
        const int idx = (blockIdx.x - 16384) * 128 + t;
        if (idx < 27 * 512) {
            const int tap = idx >> 9, r = idx & 511;
            const int co = r >> 4, cin = r & 15;
            g_w2[tap * 512 + r] = __float2half_rn(w[(co * 16 + cin) * 27 + tap]);
        }
    }
}

// ---------------- main kernel ----------------
// M = 512 rows (16 h x 32 w) per CTA; 8 warps x 4 rowtiles.
// Rows stored at 48B pitch (32B data + 16B pad) -> ldmatrix is bank-conflict-free:
// row starts at word 12i mod 32 tile all 32 banks exactly once across 8 rows x 4 words.
// dynamic smem (bytes):
//   [0, 41472)          weights: 27 taps x (32 rows x 48B) = 1536B per tap
//   [41472, 96960)      slab: 2 buffers of 27744B (578 rows x 48B)
// epilogue overlays floats at offset 0: 512 x 33 x 4 = 67584B
#define SMEM_DYN 96960
#define WPITCH   48
#define TAPSZ    1536
#define SLAB0    41472
#define BUFSZ    27744

__global__ __launch_bounds__(TPB, 2) void conv_main(
    const float* __restrict__ cbias,
    const float* __restrict__ sfac,
    const float* __restrict__ bparm,
    float* __restrict__ out)
{
    extern __shared__ char sm[];
    __shared__ float e0[32], e1[32], e2n[32];

    const int d0 = blockIdx.x, b = blockIdx.y, hh = blockIdx.z;
    const int t = threadIdx.x, warp = t >> 5, lane = t & 31;
    const uint32_t smb = smem_u32(sm);
    const uint32_t ws_a = smb;

    const int hstart = hh * 16;
    const int rows_h = hh ? 16 : 18;         // input h-rows (halo below; clipped at bottom half)
    const int chunks = rows_h * 64;          // 16B chunks per slice (2 per 32B row)

    // ---- async loads (pitched 48B rows): G0 = weights + slice kd0; G1 = slice kd1
    for (int i = t; i < 1728; i += TPB)
        cp_async16(ws_a + (uint32_t)(i >> 1) * WPITCH + (uint32_t)(i & 1) * 16,
                   (const char*)g_w2 + (long)i * 16);
    #pragma unroll
    for (int buf = 0; buf < 2; ++buf) {
        const long bo = (long)((b * 32 + d0 + buf) * 32 + hstart) * 1024;
        const uint32_t dh = smb + SLAB0 + (uint32_t)buf * BUFSZ;
        for (int i = t; i < chunks; i += TPB)
            cp_async16(dh + (uint32_t)(i >> 1) * WPITCH + (uint32_t)(i & 1) * 16,
                       (const char*)g_xt + bo + (long)i * 16);
        cp_commit();
    }

    if (t < 32) {
        const float s = sfac[t];
        e0[t] = cbias[t] * s;
        e1[t] = s;
        e2n[t] = -1.4426950408889634f * bparm[t];   // -log2(e) * bias_param
    }

    float acc[4][4][4];
    #pragma unroll
    for (int rt = 0; rt < 4; ++rt)
        #pragma unroll
        for (int j = 0; j < 4; ++j)
            #pragma unroll
            for (int k = 0; k < 4; ++k)
                acc[rt][j][k] = 0.0f;

    const uint32_t bn = (lane & 7) + ((lane & 16) >> 1);
    const uint32_t bc = (lane & 8) * 2;
    const uint32_t ar = (lane & 15);
    const uint32_t ac = (lane & 16);

    #pragma unroll
    for (int kd = 0; kd < 3; ++kd) {
        if (kd < 2) cp_wait<1>(); else cp_wait<0>();
        __syncthreads();

        const uint32_t sh_a = smb + SLAB0 + (uint32_t)(kd & 1) * BUFSZ;

        #pragma unroll
        for (int kh = 0; kh < 3; ++kh) {
            #pragma unroll
            for (int kw = 0; kw < 3; ++kw) {
                const int tap = (kd * 3 + kh) * 3 + kw;
                const uint32_t roff = (uint32_t)(kh * 32 + kw);

                // B fragments: 4 n8 coltiles (shared image, all warps)
                uint32_t bh[4][2];
                {
                    const uint32_t base = ws_a + (uint32_t)tap * TAPSZ + bn * WPITCH + bc;
                    uint32_t r0[4], r1[4];
                    ldsm4(r0, base);                       // n0-15
                    ldsm4(r1, base + 16u * WPITCH);        // n16-31
                    bh[0][0] = r0[0]; bh[0][1] = r0[1]; bh[1][0] = r0[2]; bh[1][1] = r0[3];
                    bh[2][0] = r1[0]; bh[2][1] = r1[1]; bh[3][0] = r1[2]; bh[3][1] = r1[3];
                }

                // A fragments: 4 rowtiles (M=64 per warp)
                uint32_t ah[4][4];
                const uint32_t arow0 = (uint32_t)(warp * 64) + roff + ar;
                #pragma unroll
                for (int rt = 0; rt < 4; ++rt) {
                    const uint32_t aoff = (arow0 + (uint32_t)rt * 16u) * WPITCH + ac;
                    ldsm4(ah[rt], sh_a + aoff);
                }

                #pragma unroll
                for (int rt = 0; rt < 4; ++rt)
                    #pragma unroll
                    for (int j = 0; j < 4; ++j)
                        mma_f16(acc[rt][j], ah[rt], bh[j]);
            }
        }

        // after kd0 compute: refill buf0 with slice kd2
        if (kd == 0) {
            __syncthreads();
            const long bo = (long)((b * 32 + d0 + 2) * 32 + hstart) * 1024;
            const uint32_t dh = smb + SLAB0;
            for (int i = t; i < chunks; i += TPB)
                cp_async16(dh + (uint32_t)(i >> 1) * WPITCH + (uint32_t)(i & 1) * 16,
                           (const char*)g_xt + bo + (long)i * 16);
            cp_commit();
        }
    }

    // ---- epilogue: stage accumulators to smem (pitch 33), then coalesced store
    __syncthreads();
    float* ep = (float*)sm;
    const int g  = lane >> 2;
    const int cq = 2 * (lane & 3);
    #pragma unroll
    for (int rt = 0; rt < 4; ++rt) {
        const int R = warp * 64 + rt * 16 + g;
        #pragma unroll
        for (int j = 0; j < 4; ++j) {
            const int col = j * 8 + cq;
            ep[R * 33 + col]           = acc[rt][j][0];
            ep[R * 33 + col + 1]       = acc[rt][j][1];
            ep[(R + 8) * 33 + col]     = acc[rt][j][2];
            ep[(R + 8) * 33 + col + 1] = acc[rt][j][3];
        }
    }
    __syncthreads();

    #pragma unroll
    for (int half = 0; half < 2; ++half) {
        const int r = half * 256 + t;            // 0..511
        const int h = hstart + (r >> 5);
        const int w = r & 31;
        if (w < 30 && h < 30) {
            float* ob = out + (((long)b * 32 * DO_ + d0) * 30 + h) * 30 + w;
            #pragma unroll 8
            for (int co = 0; co < 32; ++co) {
                const float v = ep[r * 33 + co];
                const float y = fmaf(v, e1[co], e0[co]);
                float th; asm("tanh.approx.f32 %0, %1;" : "=f"(th) : "f"(y));
                const float z = th * e2n[co];
                float ex; asm("ex2.approx.f32 %0, %1;" : "=f"(ex) : "f"(z));
                float sg; asm("rcp.approx.f32 %0, %1;" : "=f"(sg) : "f"(1.0f + ex));
                ob[(long)co * (DO_ * 30 * 30)] = sg;
            }
        }
    }
}

// ---------------- launch ----------------
extern "C" void kernel_launch(void* const* d_in, const int* in_sizes, int n_in,
                              void* d_out, int out_size)
{
    const float* x  = (const float*)d_in[0];
    const float* w  = (const float*)d_in[1];
    const float* cb = (const float*)d_in[2];
    const float* sf = (const float*)d_in[3];
    const float* bp = (const float*)d_in[4];
    float* out      = (float*)d_out;

    cudaFuncSetAttribute(conv_main, cudaFuncAttributeMaxDynamicSharedMemorySize, SMEM_DYN);

    xform_all<<<16384 + 108, 128>>>(x, w);

    dim3 grid(DO_, 16, 2);
    conv_main<<<grid, TPB, SMEM_DYN>>>(cb, sf, bp, out);
}

// round 11
// speedup vs baseline: 1.0551x; 1.0551x over previous
#include <cuda_runtime.h>
#include <cuda_fp16.h>
#include <cstdint>
#include <math.h>

#define DO_   30
#define TPB   256

// ---------------- device scratch (no runtime alloc) ----------------
// x transformed to [b][d][h][w][cin] fp16
__device__ __align__(16) __half g_xt[16 * 32 * 32 * 32 * 16];
// weights [tap 27][cout 32][cin 16] fp16
__device__ __align__(16) __half g_w2[27 * 32 * 16];

// ---------------- helpers ----------------
__device__ __forceinline__ uint32_t smem_u32(const void* p) {
    uint32_t a;
    asm("{ .reg .u64 t; cvta.to.shared.u64 t, %1; cvt.u32.u64 %0, t; }" : "=r"(a) : "l"(p));
    return a;
}
__device__ __forceinline__ void cp_async16(uint32_t sdst, const void* gsrc) {
    asm volatile("cp.async.cg.shared.global [%0], [%1], 16;\n" :: "r"(sdst), "l"(gsrc));
}
__device__ __forceinline__ void cp_commit() { asm volatile("cp.async.commit_group;\n" ::: "memory"); }
template<int N> __device__ __forceinline__ void cp_wait() {
    asm volatile("cp.async.wait_group %0;\n" :: "n"(N) : "memory");
}
__device__ __forceinline__ void ldsm4(uint32_t* r, uint32_t addr) {
    asm volatile("ldmatrix.sync.aligned.m8n8.x4.shared.b16 {%0,%1,%2,%3}, [%4];"
        : "=r"(r[0]), "=r"(r[1]), "=r"(r[2]), "=r"(r[3]) : "r"(addr));
}
__device__ __forceinline__ void mma_f16(float* c, const uint32_t* a, const uint32_t* b) {
    asm volatile(
        "mma.sync.aligned.m16n8k16.row.col.f32.f16.f16.f32 "
        "{%0,%1,%2,%3}, {%4,%5,%6,%7}, {%8,%9}, {%0,%1,%2,%3};"
        : "+f"(c[0]), "+f"(c[1]), "+f"(c[2]), "+f"(c[3])
        : "r"(a[0]), "r"(a[1]), "r"(a[2]), "r"(a[3]), "r"(b[0]), "r"(b[1]));
}

// ---------------- merged transform kernel ----------------
__global__ __launch_bounds__(128) void xform_all(const float* __restrict__ x,
                                                 const float* __restrict__ w)
{
    const int t = threadIdx.x;
    if (blockIdx.x < 16384) {
        __shared__ float s[16][33];
        const int blk = blockIdx.x;            // (b*32 + d)*32 + h
        const int b = blk >> 10, d = (blk >> 5) & 31, h = blk & 31;

        const int cin = t >> 3, w4 = (t & 7) << 2;
        const float4 v = *(const float4*)(x + (((long)(b * 16 + cin) << 15) + (d << 10) + (h << 5) + w4));
        s[cin][w4 + 0] = v.x; s[cin][w4 + 1] = v.y; s[cin][w4 + 2] = v.z; s[cin][w4 + 3] = v.w;
        __syncthreads();

        const long ob = (long)blk * 512;
        #pragma unroll
        for (int j = 0; j < 4; ++j) {
            const int e = t + (j << 7);        // = w*16 + cin
            const int ww = e >> 4, c = e & 15;
            g_xt[ob + e] = __float2half_rn(s[c][ww]);
        }
    } else {
        const int idx = (blockIdx.x - 16384) * 128 + t;
        if (idx < 27 * 512) {
            const int tap = idx >> 9, r = idx & 511;
            const int co = r >> 4, cin = r & 15;
            g_w2[tap * 512 + r] = __float2half_rn(w[(co * 16 + cin) * 27 + tap]);
        }
    }
}

// ---------------- main kernel ----------------
// M = 512 rows (16 h x 32 w) per CTA; 8 warps x 4 rowtiles. 32B row pitch.
// All 3 d-slices resident: NO barriers inside the 27-tap mainloop.
// dynamic smem (bytes):
//   [0, 27648)          weights [tap][32 co x 16 cin] (1024B per tap)
//   [27648, 83136)      slab: 3 slices of 18496B (578 rows x 32B; 18 h-rows + pad)
// epilogue overlays floats at offset 0: 512 x 33 x 4 = 67584B
#define SMEM_DYN 83136
#define SLAB0    27648
#define SLCSZ    18496

__global__ __launch_bounds__(TPB, 2) void conv_main(
    const float* __restrict__ cbias,
    const float* __restrict__ sfac,
    const float* __restrict__ bparm,
    float* __restrict__ out)
{
    extern __shared__ char sm[];
    __shared__ float e0[32], e1[32], e2n[32];

    const int d0 = blockIdx.x, b = blockIdx.y, hh = blockIdx.z;
    const int t = threadIdx.x, warp = t >> 5, lane = t & 31;
    const uint32_t smb = smem_u32(sm);
    const uint32_t ws_a = smb;
    const uint32_t sl_a = smb + SLAB0;

    const int hstart = hh * 16;
    const int rows_h = hh ? 16 : 18;         // input h-rows (halo below; clipped at bottom half)
    const int chunks = rows_h * 64;          // 16B chunks per slice

    // ---- async loads: weights + all 3 slices, single group
    for (int i = t; i < 1728; i += TPB)
        cp_async16(ws_a + i * 16, (const char*)g_w2 + (long)i * 16);
    #pragma unroll
    for (int d = 0; d < 3; ++d) {
        const long bo = (long)((b * 32 + d0 + d) * 32 + hstart) * 1024;
        const uint32_t dh = sl_a + (uint32_t)d * SLCSZ;
        for (int i = t; i < chunks; i += TPB)
            cp_async16(dh + i * 16, (const char*)g_xt + bo + (long)i * 16);
    }
    cp_commit();

    if (t < 32) {
        const float s = sfac[t];
        e0[t] = cbias[t] * s;
        e1[t] = s;
        e2n[t] = -1.4426950408889634f * bparm[t];   // -log2(e) * bias_param
    }

    float acc[4][4][4];
    #pragma unroll
    for (int rt = 0; rt < 4; ++rt)
        #pragma unroll
        for (int j = 0; j < 4; ++j)
            #pragma unroll
            for (int k = 0; k < 4; ++k)
                acc[rt][j][k] = 0.0f;

    const uint32_t bn = (lane & 7) + ((lane & 16) >> 1);
    const uint32_t bc = (lane & 8) * 2;
    const uint32_t ar = (lane & 15);
    const uint32_t ac = (lane & 16);

    cp_wait<0>();
    __syncthreads();

    // ---- mainloop: 27 taps, fully unrolled, barrier-free
    #pragma unroll
    for (int kd = 0; kd < 3; ++kd) {
        const uint32_t kd_a = sl_a + (uint32_t)kd * SLCSZ;
        #pragma unroll
        for (int kh = 0; kh < 3; ++kh) {
            #pragma unroll
            for (int kw = 0; kw < 3; ++kw) {
                const int tap = (kd * 3 + kh) * 3 + kw;
                const uint32_t roff = (uint32_t)(kh * 32 + kw);

                // B fragments: 4 n8 coltiles (shared image, all warps)
                uint32_t bh[4][2];
                {
                    const uint32_t base = ws_a + (uint32_t)tap * 1024u + bn * 32u + bc;
                    uint32_t r0[4], r1[4];
                    ldsm4(r0, base);            // n0-15
                    ldsm4(r1, base + 512u);     // n16-31
                    bh[0][0] = r0[0]; bh[0][1] = r0[1]; bh[1][0] = r0[2]; bh[1][1] = r0[3];
                    bh[2][0] = r1[0]; bh[2][1] = r1[1]; bh[3][0] = r1[2]; bh[3][1] = r1[3];
                }

                // A fragments: 4 rowtiles (M=64 per warp)
                uint32_t ah[4][4];
                const uint32_t arow0 = (uint32_t)(warp * 64) + roff + ar;
                #pragma unroll
                for (int rt = 0; rt < 4; ++rt) {
                    const uint32_t aoff = (arow0 + (uint32_t)rt * 16u) * 32u + ac;
                    ldsm4(ah[rt], kd_a + aoff);
                }

                #pragma unroll
                for (int rt = 0; rt < 4; ++rt)
                    #pragma unroll
                    for (int j = 0; j < 4; ++j)
                        mma_f16(acc[rt][j], ah[rt], bh[j]);
            }
        }
    }

    // ---- epilogue: stage accumulators to smem (pitch 33), then coalesced store
    __syncthreads();
    float* ep = (float*)sm;
    const int g  = lane >> 2;
    const int cq = 2 * (lane & 3);
    #pragma unroll
    for (int rt = 0; rt < 4; ++rt) {
        const int R = warp * 64 + rt * 16 + g;
        #pragma unroll
        for (int j = 0; j < 4; ++j) {
            const int col = j * 8 + cq;
            ep[R * 33 + col]           = acc[rt][j][0];
            ep[R * 33 + col + 1]       = acc[rt][j][1];
            ep[(R + 8) * 33 + col]     = acc[rt][j][2];
            ep[(R + 8) * 33 + col + 1] = acc[rt][j][3];
        }
    }
    __syncthreads();

    #pragma unroll
    for (int half = 0; half < 2; ++half) {
        const int r = half * 256 + t;            // 0..511
        const int h = hstart + (r >> 5);
        const int w = r & 31;
        if (w < 30 && h < 30) {
            float* ob = out + (((long)b * 32 * DO_ + d0) * 30 + h) * 30 + w;
            #pragma unroll 8
            for (int co = 0; co < 32; ++co) {
                const float v = ep[r * 33 + co];
                const float y = fmaf(v, e1[co], e0[co]);
                float th; asm("tanh.approx.f32 %0, %1;" : "=f"(th) : "f"(y));
                const float z = th * e2n[co];
                float ex; asm("ex2.approx.f32 %0, %1;" : "=f"(ex) : "f"(z));
                float sg; asm("rcp.approx.f32 %0, %1;" : "=f"(sg) : "f"(1.0f + ex));
                ob[(long)co * (DO_ * 30 * 30)] = sg;
            }
        }
    }
}

// ---------------- launch ----------------
extern "C" void kernel_launch(void* const* d_in, const int* in_sizes, int n_in,
                              void* d_out, int out_size)
{
    const float* x  = (const float*)d_in[0];
    const float* w  = (const float*)d_in[1];
    const float* cb = (const float*)d_in[2];
    const float* sf = (const float*)d_in[3];
    const float* bp = (const float*)d_in[4];
    float* out      = (float*)d_out;

    cudaFuncSetAttribute(conv_main, cudaFuncAttributeMaxDynamicSharedMemorySize, SMEM_DYN);

    xform_all<<<16384 + 108, 128>>>(x, w);

    dim3 grid(DO_, 16, 2);
    conv_main<<<grid, TPB, SMEM_DYN>>>(cb, sf, bp, out);
}

// round 12
// speedup vs baseline: 1.1167x; 1.0584x over previous
#include <cuda_runtime.h>
#include <cuda_fp16.h>
#include <cstdint>
#include <math.h>

#define DO_   30
#define TPB   256

// ---------------- device scratch (no runtime alloc) ----------------
// x transformed to [b][d][h][w][cin] fp16
__device__ __align__(16) __half g_xt[16 * 32 * 32 * 32 * 16];
// weights [tap 27][cout 32][cin 16] fp16
__device__ __align__(16) __half g_w2[27 * 32 * 16];

// ---------------- helpers ----------------
__device__ __forceinline__ uint32_t smem_u32(const void* p) {
    uint32_t a;
    asm("{ .reg .u64 t; cvta.to.shared.u64 t, %1; cvt.u32.u64 %0, t; }" : "=r"(a) : "l"(p));
    return a;
}
__device__ __forceinline__ void cp_async16(uint32_t sdst, const void* gsrc) {
    asm volatile("cp.async.cg.shared.global [%0], [%1], 16;\n" :: "r"(sdst), "l"(gsrc));
}
__device__ __forceinline__ void cp_commit() { asm volatile("cp.async.commit_group;\n" ::: "memory"); }
template<int N> __device__ __forceinline__ void cp_wait() {
    asm volatile("cp.async.wait_group %0;\n" :: "n"(N) : "memory");
}
__device__ __forceinline__ void ldsm4(uint32_t* r, uint32_t addr) {
    asm volatile("ldmatrix.sync.aligned.m8n8.x4.shared.b16 {%0,%1,%2,%3}, [%4];"
        : "=r"(r[0]), "=r"(r[1]), "=r"(r[2]), "=r"(r[3]) : "r"(addr));
}
__device__ __forceinline__ void mma_f16(float* c, const uint32_t* a, const uint32_t* b) {
    asm volatile(
        "mma.sync.aligned.m16n8k16.row.col.f32.f16.f16.f32 "
        "{%0,%1,%2,%3}, {%4,%5,%6,%7}, {%8,%9}, {%0,%1,%2,%3};"
        : "+f"(c[0]), "+f"(c[1]), "+f"(c[2]), "+f"(c[3])
        : "r"(a[0]), "r"(a[1]), "r"(a[2]), "r"(a[3]), "r"(b[0]), "r"(b[1]));
}

// Swizzle: row's two 16B chunks placed at chunk ^ ((row>>2)&1).
// Makes every ldmatrix 8x8 matrix read (8 rows x 16B at 32B pitch) hit all
// 32 banks exactly once (words 0,8,16,24,4,12,20,28).
__device__ __forceinline__ uint32_t swz(uint32_t row, uint32_t chunk16) {
    return row * 32u + (chunk16 ^ ((row & 4u) << 2));
}

// ---------------- merged transform kernel ----------------
__global__ __launch_bounds__(128) void xform_all(const float* __restrict__ x,
                                                 const float* __restrict__ w)
{
    const int t = threadIdx.x;
    if (blockIdx.x < 16384) {
        __shared__ float s[16][33];
        const int blk = blockIdx.x;            // (b*32 + d)*32 + h
        const int b = blk >> 10, d = (blk >> 5) & 31, h = blk & 31;

        const int cin = t >> 3, w4 = (t & 7) << 2;
        const float4 v = *(const float4*)(x + (((long)(b * 16 + cin) << 15) + (d << 10) + (h << 5) + w4));
        s[cin][w4 + 0] = v.x; s[cin][w4 + 1] = v.y; s[cin][w4 + 2] = v.z; s[cin][w4 + 3] = v.w;
        __syncthreads();

        const long ob = (long)blk * 512;
        #pragma unroll
        for (int j = 0; j < 4; ++j) {
            const int e = t + (j << 7);        // = w*16 + cin
            const int ww = e >> 4, c = e & 15;
            g_xt[ob + e] = __float2half_rn(s[c][ww]);
        }
    } else {
        const int idx = (blockIdx.x - 16384) * 128 + t;
        if (idx < 27 * 512) {
            const int tap = idx >> 9, r = idx & 511;
            const int co = r >> 4, cin = r & 15;
            g_w2[tap * 512 + r] = __float2half_rn(w[(co * 16 + cin) * 27 + tap]);
        }
    }
}

// ---------------- main kernel ----------------
// M = 512 rows (16 h x 32 w) per CTA; 8 warps x 4 rowtiles. 32B row pitch,
// XOR-16B swizzle. All 3 d-slices resident; no barriers in the 27-tap loop.
// dynamic smem (bytes):
//   [0, 27648)          weights [tap][32 co x 16 cin] (1024B per tap, swizzled)
//   [27648, 83136)      slab: 3 slices of 18496B (578 rows x 32B, swizzled)
// epilogue overlays floats at offset 0: 512 x 33 x 4 = 67584B
#define SMEM_DYN 83136
#define SLAB0    27648
#define SLCSZ    18496

__global__ __launch_bounds__(TPB, 2) void conv_main(
    const float* __restrict__ cbias,
    const float* __restrict__ sfac,
    const float* __restrict__ bparm,
    float* __restrict__ out)
{
    extern __shared__ char sm[];
    __shared__ float e0[32], e1[32], e2n[32];

    const int d0 = blockIdx.x, b = blockIdx.y, hh = blockIdx.z;
    const int t = threadIdx.x, warp = t >> 5, lane = t & 31;
    const uint32_t smb = smem_u32(sm);
    const uint32_t ws_a = smb;
    const uint32_t sl_a = smb + SLAB0;

    const int hstart = hh * 16;
    const int rows_h = hh ? 16 : 18;         // input h-rows (halo below; clipped at bottom half)
    const int chunks = rows_h * 64;          // 16B chunks per slice

    // ---- async loads (swizzled dst): weights + all 3 slices, single group
    for (int i = t; i < 1728; i += TPB)
        cp_async16(ws_a + swz((uint32_t)(i >> 1), (uint32_t)(i & 1) << 4),
                   (const char*)g_w2 + (long)i * 16);
    #pragma unroll
    for (int d = 0; d < 3; ++d) {
        const long bo = (long)((b * 32 + d0 + d) * 32 + hstart) * 1024;
        const uint32_t dh = sl_a + (uint32_t)d * SLCSZ;
        for (int i = t; i < chunks; i += TPB)
            cp_async16(dh + swz((uint32_t)(i >> 1), (uint32_t)(i & 1) << 4),
                       (const char*)g_xt + bo + (long)i * 16);
    }
    cp_commit();

    if (t < 32) {
        const float s = sfac[t];
        e0[t] = cbias[t] * s;
        e1[t] = s;
        e2n[t] = -1.4426950408889634f * bparm[t];   // -log2(e) * bias_param
    }

    float acc[4][4][4];
    #pragma unroll
    for (int rt = 0; rt < 4; ++rt)
        #pragma unroll
        for (int j = 0; j < 4; ++j)
            #pragma unroll
            for (int k = 0; k < 4; ++k)
                acc[rt][j][k] = 0.0f;

    const uint32_t bn = (lane & 7) + ((lane & 16) >> 1);
    const uint32_t bc = (lane & 8) * 2;
    const uint32_t ar = (lane & 15);
    const uint32_t ac = (lane & 16);

    // B lane address within a tap tile (row = bn; tap*32 doesn't affect row&4)
    const uint32_t bofs = swz(bn, bc);                 // n0-15 image
    const uint32_t bofs2 = swz(bn + 16u, bc);          // n16-31 image

    cp_wait<0>();
    __syncthreads();

    // ---- mainloop: 27 taps, fully unrolled, barrier-free
    #pragma unroll
    for (int kd = 0; kd < 3; ++kd) {
        const uint32_t kd_a = sl_a + (uint32_t)kd * SLCSZ;
        #pragma unroll
        for (int kh = 0; kh < 3; ++kh) {
            #pragma unroll
            for (int kw = 0; kw < 3; ++kw) {
                const int tap = (kd * 3 + kh) * 3 + kw;
                const uint32_t roff = (uint32_t)(kh * 32 + kw);

                // B fragments: 4 n8 coltiles (shared image, all warps)
                uint32_t bh[4][2];
                {
                    const uint32_t base = ws_a + (uint32_t)tap * 1024u;
                    uint32_t r0[4], r1[4];
                    ldsm4(r0, base + bofs);     // n0-15
                    ldsm4(r1, base + bofs2);    // n16-31
                    bh[0][0] = r0[0]; bh[0][1] = r0[1]; bh[1][0] = r0[2]; bh[1][1] = r0[3];
                    bh[2][0] = r1[0]; bh[2][1] = r1[1]; bh[3][0] = r1[2]; bh[3][1] = r1[3];
                }

                // A fragments: 4 rowtiles (M=64 per warp)
                uint32_t ah[4][4];
                const uint32_t arow0 = (uint32_t)(warp * 64) + roff + ar;
                const uint32_t axor = ac ^ ((arow0 & 4u) << 2);  // rt*16 keeps row&4
                #pragma unroll
                for (int rt = 0; rt < 4; ++rt) {
                    const uint32_t aoff = (arow0 + (uint32_t)rt * 16u) * 32u + axor;
                    ldsm4(ah[rt], kd_a + aoff);
                }

                #pragma unroll
                for (int rt = 0; rt < 4; ++rt)
                    #pragma unroll
                    for (int j = 0; j < 4; ++j)
                        mma_f16(acc[rt][j], ah[rt], bh[j]);
            }
        }
    }

    // ---- epilogue: stage accumulators to smem (pitch 33), then coalesced store
    __syncthreads();
    float* ep = (float*)sm;
    const int g  = lane >> 2;
    const int cq = 2 * (lane & 3);
    #pragma unroll
    for (int rt = 0; rt < 4; ++rt) {
        const int R = warp * 64 + rt * 16 + g;
        #pragma unroll
        for (int j = 0; j < 4; ++j) {
            const int col = j * 8 + cq;
            ep[R * 33 + col]           = acc[rt][j][0];
            ep[R * 33 + col + 1]       = acc[rt][j][1];
            ep[(R + 8) * 33 + col]     = acc[rt][j][2];
            ep[(R + 8) * 33 + col + 1] = acc[rt][j][3];
        }
    }
    __syncthreads();

    #pragma unroll
    for (int half = 0; half < 2; ++half) {
        const int r = half * 256 + t;            // 0..511
        const int h = hstart + (r >> 5);
        const int w = r & 31;
        if (w < 30 && h < 30) {
            float* ob = out + (((long)b * 32 * DO_ + d0) * 30 + h) * 30 + w;
            #pragma unroll 8
            for (int co = 0; co < 32; ++co) {
                const float v = ep[r * 33 + co];
                const float y = fmaf(v, e1[co], e0[co]);
                float th; asm("tanh.approx.f32 %0, %1;" : "=f"(th) : "f"(y));
                const float z = th * e2n[co];
                float ex; asm("ex2.approx.f32 %0, %1;" : "=f"(ex) : "f"(z));
                float sg; asm("rcp.approx.f32 %0, %1;" : "=f"(sg) : "f"(1.0f + ex));
                ob[(long)co * (DO_ * 30 * 30)] = sg;
            }
        }
    }
}

// ---------------- launch ----------------
extern "C" void kernel_launch(void* const* d_in, const int* in_sizes, int n_in,
                              void* d_out, int out_size)
{
    const float* x  = (const float*)d_in[0];
    const float* w  = (const float*)d_in[1];
    const float* cb = (const float*)d_in[2];
    const float* sf = (const float*)d_in[3];
    const float* bp = (const float*)d_in[4];
    float* out      = (float*)d_out;

    cudaFuncSetAttribute(conv_main, cudaFuncAttributeMaxDynamicSharedMemorySize, SMEM_DYN);

    xform_all<<<16384 + 108, 128>>>(x, w);

    dim3 grid(DO_, 16, 2);
    conv_main<<<grid, TPB, SMEM_DYN>>>(cb, sf, bp, out);
}

// round 13
// speedup vs baseline: 1.1185x; 1.0016x over previous
#include <cuda_runtime.h>
#include <cuda_fp16.h>
#include <cstdint>
#include <math.h>

#define DO_   30
#define TPB   512

// ---------------- device scratch (no runtime alloc) ----------------
// x transformed to [b][d][h][w][cin] fp16
__device__ __align__(16) __half g_xt[16 * 32 * 32 * 32 * 16];
// weights [tap 27][cout 32][cin 16] fp16
__device__ __align__(16) __half g_w2[27 * 32 * 16];

// ---------------- helpers ----------------
__device__ __forceinline__ uint32_t smem_u32(const void* p) {
    uint32_t a;
    asm("{ .reg .u64 t; cvta.to.shared.u64 t, %1; cvt.u32.u64 %0, t; }" : "=r"(a) : "l"(p));
    return a;
}
__device__ __forceinline__ void cp_async16(uint32_t sdst, const void* gsrc) {
    asm volatile("cp.async.cg.shared.global [%0], [%1], 16;\n" :: "r"(sdst), "l"(gsrc));
}
__device__ __forceinline__ void cp_commit() { asm volatile("cp.async.commit_group;\n" ::: "memory"); }
template<int N> __device__ __forceinline__ void cp_wait() {
    asm volatile("cp.async.wait_group %0;\n" :: "n"(N) : "memory");
}
__device__ __forceinline__ void ldsm4(uint32_t* r, uint32_t addr) {
    asm volatile("ldmatrix.sync.aligned.m8n8.x4.shared.b16 {%0,%1,%2,%3}, [%4];"
        : "=r"(r[0]), "=r"(r[1]), "=r"(r[2]), "=r"(r[3]) : "r"(addr));
}
__device__ __forceinline__ void mma_f16(float* c, const uint32_t* a, const uint32_t* b) {
    asm volatile(
        "mma.sync.aligned.m16n8k16.row.col.f32.f16.f16.f32 "
        "{%0,%1,%2,%3}, {%4,%5,%6,%7}, {%8,%9}, {%0,%1,%2,%3};"
        : "+f"(c[0]), "+f"(c[1]), "+f"(c[2]), "+f"(c[3])
        : "r"(a[0]), "r"(a[1]), "r"(a[2]), "r"(a[3]), "r"(b[0]), "r"(b[1]));
}

// Swizzle: row's two 16B chunks placed at chunk ^ ((row>>2)&1).
// ldmatrix 8x8 reads (8 rows x 16B at 32B pitch) then hit all 32 banks once.
__device__ __forceinline__ uint32_t swz(uint32_t row, uint32_t chunk16) {
    return row * 32u + (chunk16 ^ ((row & 4u) << 2));
}

// ---------------- merged transform kernel ----------------
__global__ __launch_bounds__(128) void xform_all(const float* __restrict__ x,
                                                 const float* __restrict__ w)
{
    const int t = threadIdx.x;
    if (blockIdx.x < 16384) {
        __shared__ float s[16][33];
        const int blk = blockIdx.x;            // (b*32 + d)*32 + h
        const int b = blk >> 10, d = (blk >> 5) & 31, h = blk & 31;

        const int cin = t >> 3, w4 = (t & 7) << 2;
        const float4 v = *(const float4*)(x + (((long)(b * 16 + cin) << 15) + (d << 10) + (h << 5) + w4));
        s[cin][w4 + 0] = v.x; s[cin][w4 + 1] = v.y; s[cin][w4 + 2] = v.z; s[cin][w4 + 3] = v.w;
        __syncthreads();

        const long ob = (long)blk * 512;
        #pragma unroll
        for (int j = 0; j < 4; ++j) {
            const int e = t + (j << 7);        // = w*16 + cin
            const int ww = e >> 4, c = e & 15;
            g_xt[ob + e] = __float2half_rn(s[c][ww]);
        }
    } else {
        const int idx = (blockIdx.x - 16384) * 128 + t;
        if (idx < 27 * 512) {
            const int tap = idx >> 9, r = idx & 511;
            const int co = r >> 4, cin = r & 15;
            g_w2[tap * 512 + r] = __float2half_rn(w[(co * 16 + cin) * 27 + tap]);
        }
    }
}

// ---------------- main kernel ----------------
// M = 512 rows (16 h x 32 w) per CTA; 16 warps x 2 rowtiles (512 threads).
// 32B row pitch + XOR-16B swizzle; 3 resident d-slices; barrier-free mainloop.
// dynamic smem (bytes):
//   [0, 27648)          weights [tap][32 co x 16 cin] (1024B per tap, swizzled)
//   [27648, 83136)      slab: 3 slices of 18496B (578 rows x 32B, swizzled)
// epilogue overlays floats at offset 0: 512 x 33 x 4 = 67584B
#define SMEM_DYN 83136
#define SLAB0    27648
#define SLCSZ    18496

__global__ __launch_bounds__(TPB, 2) void conv_main(
    const float* __restrict__ cbias,
    const float* __restrict__ sfac,
    const float* __restrict__ bparm,
    float* __restrict__ out)
{
    extern __shared__ char sm[];
    __shared__ float e0[32], e1[32], e2n[32];

    const int d0 = blockIdx.x, b = blockIdx.y, hh = blockIdx.z;
    const int t = threadIdx.x, warp = t >> 5, lane = t & 31;
    const uint32_t smb = smem_u32(sm);
    const uint32_t ws_a = smb;
    const uint32_t sl_a = smb + SLAB0;

    const int hstart = hh * 16;
    const int rows_h = hh ? 16 : 18;         // input h-rows (halo below; clipped at bottom half)
    const int chunks = rows_h * 64;          // 16B chunks per slice

    // ---- async loads (swizzled dst): weights + all 3 slices, single group
    for (int i = t; i < 1728; i += TPB)
        cp_async16(ws_a + swz((uint32_t)(i >> 1), (uint32_t)(i & 1) << 4),
                   (const char*)g_w2 + (long)i * 16);
    #pragma unroll
    for (int d = 0; d < 3; ++d) {
        const long bo = (long)((b * 32 + d0 + d) * 32 + hstart) * 1024;
        const uint32_t dh = sl_a + (uint32_t)d * SLCSZ;
        for (int i = t; i < chunks; i += TPB)
            cp_async16(dh + swz((uint32_t)(i >> 1), (uint32_t)(i & 1) << 4),
                       (const char*)g_xt + bo + (long)i * 16);
    }
    cp_commit();

    if (t < 32) {
        const float s = sfac[t];
        e0[t] = cbias[t] * s;
        e1[t] = s;
        e2n[t] = -1.4426950408889634f * bparm[t];   // -log2(e) * bias_param
    }

    float acc[2][4][4];
    #pragma unroll
    for (int rt = 0; rt < 2; ++rt)
        #pragma unroll
        for (int j = 0; j < 4; ++j)
            #pragma unroll
            for (int k = 0; k < 4; ++k)
                acc[rt][j][k] = 0.0f;

    const uint32_t bn = (lane & 7) + ((lane & 16) >> 1);
    const uint32_t bc = (lane & 8) * 2;
    const uint32_t ar = (lane & 15);
    const uint32_t ac = (lane & 16);

    const uint32_t bofs  = swz(bn, bc);                // n0-15 image
    const uint32_t bofs2 = swz(bn + 16u, bc);          // n16-31 image

    cp_wait<0>();
    __syncthreads();

    // ---- mainloop: 27 taps, fully unrolled, barrier-free
    #pragma unroll
    for (int kd = 0; kd < 3; ++kd) {
        const uint32_t kd_a = sl_a + (uint32_t)kd * SLCSZ;
        #pragma unroll
        for (int kh = 0; kh < 3; ++kh) {
            #pragma unroll
            for (int kw = 0; kw < 3; ++kw) {
                const int tap = (kd * 3 + kh) * 3 + kw;
                const uint32_t roff = (uint32_t)(kh * 32 + kw);

                // B fragments: 4 n8 coltiles
                uint32_t bh[4][2];
                {
                    const uint32_t base = ws_a + (uint32_t)tap * 1024u;
                    uint32_t r0[4], r1[4];
                    ldsm4(r0, base + bofs);     // n0-15
                    ldsm4(r1, base + bofs2);    // n16-31
                    bh[0][0] = r0[0]; bh[0][1] = r0[1]; bh[1][0] = r0[2]; bh[1][1] = r0[3];
                    bh[2][0] = r1[0]; bh[2][1] = r1[1]; bh[3][0] = r1[2]; bh[3][1] = r1[3];
                }

                // A fragments: 2 rowtiles (M=32 per warp)
                uint32_t ah[2][4];
                const uint32_t arow0 = (uint32_t)(warp * 32) + roff + ar;
                const uint32_t axor = ac ^ ((arow0 & 4u) << 2);  // rt*16 keeps row&4
                #pragma unroll
                for (int rt = 0; rt < 2; ++rt) {
                    const uint32_t aoff = (arow0 + (uint32_t)rt * 16u) * 32u + axor;
                    ldsm4(ah[rt], kd_a + aoff);
                }

                #pragma unroll
                for (int rt = 0; rt < 2; ++rt)
                    #pragma unroll
                    for (int j = 0; j < 4; ++j)
                        mma_f16(acc[rt][j], ah[rt], bh[j]);
            }
        }
    }

    // ---- epilogue: stage accumulators to smem (pitch 33), then coalesced store
    __syncthreads();
    float* ep = (float*)sm;
    const int g  = lane >> 2;
    const int cq = 2 * (lane & 3);
    #pragma unroll
    for (int rt = 0; rt < 2; ++rt) {
        const int R = warp * 32 + rt * 16 + g;
        #pragma unroll
        for (int j = 0; j < 4; ++j) {
            const int col = j * 8 + cq;
            ep[R * 33 + col]           = acc[rt][j][0];
            ep[R * 33 + col + 1]       = acc[rt][j][1];
            ep[(R + 8) * 33 + col]     = acc[rt][j][2];
            ep[(R + 8) * 33 + col + 1] = acc[rt][j][3];
        }
    }
    __syncthreads();

    {
        const int r = t;                         // 0..511
        const int h = hstart + (r >> 5);
        const int w = r & 31;
        if (w < 30 && h < 30) {
            float* ob = out + (((long)b * 32 * DO_ + d0) * 30 + h) * 30 + w;
            #pragma unroll 8
            for (int co = 0; co < 32; ++co) {
                const float v = ep[r * 33 + co];
                const float y = fmaf(v, e1[co], e0[co]);
                float th; asm("tanh.approx.f32 %0, %1;" : "=f"(th) : "f"(y));
                const float z = th * e2n[co];
                float ex; asm("ex2.approx.f32 %0, %1;" : "=f"(ex) : "f"(z));
                float sg; asm("rcp.approx.f32 %0, %1;" : "=f"(sg) : "f"(1.0f + ex));
                ob[(long)co * (DO_ * 30 * 30)] = sg;
            }
        }
    }
}

// ---------------- launch ----------------
extern "C" void kernel_launch(void* const* d_in, const int* in_sizes, int n_in,
                              void* d_out, int out_size)
{
    const float* x  = (const float*)d_in[0];
    const float* w  = (const float*)d_in[1];
    const float* cb = (const float*)d_in[2];
    const float* sf = (const float*)d_in[3];
    const float* bp = (const float*)d_in[4];
    float* out      = (float*)d_out;

    cudaFuncSetAttribute(conv_main, cudaFuncAttributeMaxDynamicSharedMemorySize, SMEM_DYN);

    xform_all<<<16384 + 108, 128>>>(x, w);

    dim3 grid(DO_, 16, 2);
    conv_main<<<grid, TPB, SMEM_DYN>>>(cb, sf, bp, out);
}

// round 14
// speedup vs baseline: 1.1284x; 1.0089x over previous
#include <cuda_runtime.h>
#include <cuda_fp16.h>
#include <cstdint>
#include <math.h>

#define DO_   30
#define TPB   256

// ---------------- device scratch (no runtime alloc) ----------------
__device__ __align__(16) __half g_xt[16 * 32 * 32 * 32 * 16];
__device__ __align__(16) __half g_w2[27 * 32 * 16];

// ---------------- helpers ----------------
__device__ __forceinline__ uint32_t smem_u32(const void* p) {
    uint32_t a;
    asm("{ .reg .u64 t; cvta.to.shared.u64 t, %1; cvt.u32.u64 %0, t; }" : "=r"(a) : "l"(p));
    return a;
}
__device__ __forceinline__ void cp_async16(uint32_t sdst, const void* gsrc) {
    asm volatile("cp.async.cg.shared.global [%0], [%1], 16;\n" :: "r"(sdst), "l"(gsrc));
}
__device__ __forceinline__ void cp_commit() { asm volatile("cp.async.commit_group;\n" ::: "memory"); }
template<int N> __device__ __forceinline__ void cp_wait() {
    asm volatile("cp.async.wait_group %0;\n" :: "n"(N) : "memory");
}
__device__ __forceinline__ void ldsm4(uint32_t* r, uint32_t addr) {
    asm volatile("ldmatrix.sync.aligned.m8n8.x4.shared.b16 {%0,%1,%2,%3}, [%4];"
        : "=r"(r[0]), "=r"(r[1]), "=r"(r[2]), "=r"(r[3]) : "r"(addr));
}
__device__ __forceinline__ void mma_f16(float* c, const uint32_t* a, const uint32_t* b) {
    asm volatile(
        "mma.sync.aligned.m16n8k16.row.col.f32.f16.f16.f32 "
        "{%0,%1,%2,%3}, {%4,%5,%6,%7}, {%8,%9}, {%0,%1,%2,%3};"
        : "+f"(c[0]), "+f"(c[1]), "+f"(c[2]), "+f"(c[3])
        : "r"(a[0]), "r"(a[1]), "r"(a[2]), "r"(a[3]), "r"(b[0]), "r"(b[1]));
}

// Swizzle: row's two 16B chunks at chunk ^ ((row>>2)&1) -> conflict-free ldmatrix.
__device__ __forceinline__ uint32_t swz(uint32_t row, uint32_t chunk16) {
    return row * 32u + (chunk16 ^ ((row & 4u) << 2));
}

// ---------------- merged transform kernel ----------------
__global__ __launch_bounds__(128) void xform_all(const float* __restrict__ x,
                                                 const float* __restrict__ w)
{
    const int t = threadIdx.x;
    if (blockIdx.x < 16384) {
        __shared__ float s[16][33];
        const int blk = blockIdx.x;            // (b*32 + d)*32 + h
        const int b = blk >> 10, d = (blk >> 5) & 31, h = blk & 31;

        const int cin = t >> 3, w4 = (t & 7) << 2;
        const float4 v = *(const float4*)(x + (((long)(b * 16 + cin) << 15) + (d << 10) + (h << 5) + w4));
        s[cin][w4 + 0] = v.x; s[cin][w4 + 1] = v.y; s[cin][w4 + 2] = v.z; s[cin][w4 + 3] = v.w;
        __syncthreads();

        const long ob = (long)blk * 512;
        #pragma unroll
        for (int j = 0; j < 4; ++j) {
            const int e = t + (j << 7);        // = w*16 + cin
            const int ww = e >> 4, c = e & 15;
            g_xt[ob + e] = __float2half_rn(s[c][ww]);
        }
    } else {
        const int idx = (blockIdx.x - 16384) * 128 + t;
        if (idx < 27 * 512) {
            const int tap = idx >> 9, r = idx & 511;
            const int co = r >> 4, cin = r & 15;
            g_w2[tap * 512 + r] = __float2half_rn(w[(co * 16 + cin) * 27 + tap]);
        }
    }
}

// ---------------- main kernel ----------------
// M = 512 rows per CTA; 8 warps x 4 rowtiles (256 threads). 32B pitch + XOR swizzle.
// 3 resident d-slices; barrier-free mainloop; A fragments double-buffered so
// tap n+1's LDSM issues under tap n's MMAs.
#define SMEM_DYN 83136
#define SLAB0    27648
#define SLCSZ    18496

__global__ __launch_bounds__(TPB, 2) void conv_main(
    const float* __restrict__ cbias,
    const float* __restrict__ sfac,
    const float* __restrict__ bparm,
    float* __restrict__ out)
{
    extern __shared__ char sm[];
    __shared__ float e0[32], e1[32], e2n[32];

    const int d0 = blockIdx.x, b = blockIdx.y, hh = blockIdx.z;
    const int t = threadIdx.x, warp = t >> 5, lane = t & 31;
    const uint32_t smb = smem_u32(sm);
    const uint32_t ws_a = smb;
    const uint32_t sl_a = smb + SLAB0;

    const int hstart = hh * 16;
    const int rows_h = hh ? 16 : 18;
    const int chunks = rows_h * 64;

    // ---- async loads (swizzled dst): weights + all 3 slices
    for (int i = t; i < 1728; i += TPB)
        cp_async16(ws_a + swz((uint32_t)(i >> 1), (uint32_t)(i & 1) << 4),
                   (const char*)g_w2 + (long)i * 16);
    #pragma unroll
    for (int d = 0; d < 3; ++d) {
        const long bo = (long)((b * 32 + d0 + d) * 32 + hstart) * 1024;
        const uint32_t dh = sl_a + (uint32_t)d * SLCSZ;
        for (int i = t; i < chunks; i += TPB)
            cp_async16(dh + swz((uint32_t)(i >> 1), (uint32_t)(i & 1) << 4),
                       (const char*)g_xt + bo + (long)i * 16);
    }
    cp_commit();

    if (t < 32) {
        const float s = sfac[t];
        e0[t] = cbias[t] * s;
        e1[t] = s;
        e2n[t] = -1.4426950408889634f * bparm[t];
    }

    float acc[4][4][4];
    #pragma unroll
    for (int rt = 0; rt < 4; ++rt)
        #pragma unroll
        for (int j = 0; j < 4; ++j)
            #pragma unroll
            for (int k = 0; k < 4; ++k)
                acc[rt][j][k] = 0.0f;

    const uint32_t bn = (lane & 7) + ((lane & 16) >> 1);
    const uint32_t bc = (lane & 8) * 2;
    const uint32_t ar = (lane & 15);
    const uint32_t ac = (lane & 16);

    const uint32_t bofs  = swz(bn, bc);
    const uint32_t bofs2 = swz(bn + 16u, bc);

    cp_wait<0>();
    __syncthreads();

    // ---- software-pipelined mainloop over 27 taps
    // A-fragment address for tap idx (kd = idx/9, kh = (idx%9)/3, kw = idx%3)
    const uint32_t awbase = (uint32_t)(warp * 64) + ar;

    uint32_t ah[2][4][4];       // double-buffered A fragments
    uint32_t bh[4][2];          // B fragments (single buffer)

    // preload A for tap 0
    {
        const uint32_t arow0 = awbase;      // kd=kh=kw=0
        const uint32_t axor = ac ^ ((arow0 & 4u) << 2);
        #pragma unroll
        for (int rt = 0; rt < 4; ++rt)
            ldsm4(ah[0][rt], sl_a + (arow0 + (uint32_t)rt * 16u) * 32u + axor);
    }

    #pragma unroll
    for (int tap = 0; tap < 27; ++tap) {
        const int buf = tap & 1;

        // B fragments for current tap
        {
            const uint32_t base = ws_a + (uint32_t)tap * 1024u;
            uint32_t r0[4], r1[4];
            ldsm4(r0, base + bofs);
            ldsm4(r1, base + bofs2);
            bh[0][0] = r0[0]; bh[0][1] = r0[1]; bh[1][0] = r0[2]; bh[1][1] = r0[3];
            bh[2][0] = r1[0]; bh[2][1] = r1[1]; bh[3][0] = r1[2]; bh[3][1] = r1[3];
        }

        // prefetch A for tap+1 into the alternate buffer
        if (tap + 1 < 27) {
            const int nt = tap + 1;
            const int nkd = nt / 9, nr = nt - nkd * 9;
            const int nkh = nr / 3, nkw = nr - nkh * 3;
            const uint32_t arow0 = awbase + (uint32_t)(nkh * 32 + nkw);
            const uint32_t axor = ac ^ ((arow0 & 4u) << 2);
            const uint32_t kd_a = sl_a + (uint32_t)nkd * SLCSZ;
            #pragma unroll
            for (int rt = 0; rt < 4; ++rt)
                ldsm4(ah[buf ^ 1][rt], kd_a + (arow0 + (uint32_t)rt * 16u) * 32u + axor);
        }

        // MMAs for current tap (each acc element touched once -> no chains)
        #pragma unroll
        for (int rt = 0; rt < 4; ++rt)
            #pragma unroll
            for (int j = 0; j < 4; ++j)
                mma_f16(acc[rt][j], ah[buf][rt], bh[j]);
    }

    // ---- epilogue: stage accumulators to smem (pitch 33), then coalesced store
    __syncthreads();
    float* ep = (float*)sm;
    const int g  = lane >> 2;
    const int cq = 2 * (lane & 3);
    #pragma unroll
    for (int rt = 0; rt < 4; ++rt) {
        const int R = warp * 64 + rt * 16 + g;
        #pragma unroll
        for (int j = 0; j < 4; ++j) {
            const int col = j * 8 + cq;
            ep[R * 33 + col]           = acc[rt][j][0];
            ep[R * 33 + col + 1]       = acc[rt][j][1];
            ep[(R + 8) * 33 + col]     = acc[rt][j][2];
            ep[(R + 8) * 33 + col + 1] = acc[rt][j][3];
        }
    }
    __syncthreads();

    #pragma unroll
    for (int half = 0; half < 2; ++half) {
        const int r = half * 256 + t;
        const int h = hstart + (r >> 5);
        const int w = r & 31;
        if (w < 30 && h < 30) {
            float* ob = out + (((long)b * 32 * DO_ + d0) * 30 + h) * 30 + w;
            #pragma unroll 8
            for (int co = 0; co < 32; ++co) {
                const float v = ep[r * 33 + co];
                const float y = fmaf(v, e1[co], e0[co]);
                float th; asm("tanh.approx.f32 %0, %1;" : "=f"(th) : "f"(y));
                const float z = th * e2n[co];
                float ex; asm("ex2.approx.f32 %0, %1;" : "=f"(ex) : "f"(z));
                float sg; asm("rcp.approx.f32 %0, %1;" : "=f"(sg) : "f"(1.0f + ex));
                ob[(long)co * (DO_ * 30 * 30)] = sg;
            }
        }
    }
}

// ---------------- launch ----------------
extern "C" void kernel_launch(void* const* d_in, const int* in_sizes, int n_in,
                              void* d_out, int out_size)
{
    const float* x  = (const float*)d_in[0];
    const float* w  = (const float*)d_in[1];
    const float* cb = (const float*)d_in[2];
    const float* sf = (const float*)d_in[3];
    const float* bp = (const float*)d_in[4];
    float* out      = (float*)d_out;

    cudaFuncSetAttribute(conv_main, cudaFuncAttributeMaxDynamicSharedMemorySize, SMEM_DYN);

    xform_all<<<16384 + 108, 128>>>(x, w);

    dim3 grid(DO_, 16, 2);
    conv_main<<<grid, TPB, SMEM_DYN>>>(cb, sf, bp, out);
}

// round 15
// speedup vs baseline: 1.1500x; 1.0191x over previous
#include <cuda_runtime.h>
#include <cuda_fp16.h>
#include <cstdint>
#include <math.h>

#define DO_   30
#define TPB   256

// ---------------- device scratch (no runtime alloc) ----------------
__device__ __align__(16) __half g_xt[16 * 32 * 32 * 32 * 16];   // [b][d][h][w][cin]
__device__ __align__(16) __half g_w2[27 * 32 * 16];             // [tap][cout][cin]

// ---------------- helpers ----------------
__device__ __forceinline__ uint32_t smem_u32(const void* p) {
    uint32_t a;
    asm("{ .reg .u64 t; cvta.to.shared.u64 t, %1; cvt.u32.u64 %0, t; }" : "=r"(a) : "l"(p));
    return a;
}
__device__ __forceinline__ void cp_async16(uint32_t sdst, const void* gsrc) {
    asm volatile("cp.async.cg.shared.global [%0], [%1], 16;\n" :: "r"(sdst), "l"(gsrc));
}
__device__ __forceinline__ void cp_commit() { asm volatile("cp.async.commit_group;\n" ::: "memory"); }
template<int N> __device__ __forceinline__ void cp_wait() {
    asm volatile("cp.async.wait_group %0;\n" :: "n"(N) : "memory");
}
__device__ __forceinline__ void ldsm4(uint32_t* r, uint32_t addr) {
    asm volatile("ldmatrix.sync.aligned.m8n8.x4.shared.b16 {%0,%1,%2,%3}, [%4];"
        : "=r"(r[0]), "=r"(r[1]), "=r"(r[2]), "=r"(r[3]) : "r"(addr));
}
__device__ __forceinline__ void mma_f16(float* c, const uint32_t* a, const uint32_t* b) {
    asm volatile(
        "mma.sync.aligned.m16n8k16.row.col.f32.f16.f16.f32 "
        "{%0,%1,%2,%3}, {%4,%5,%6,%7}, {%8,%9}, {%0,%1,%2,%3};"
        : "+f"(c[0]), "+f"(c[1]), "+f"(c[2]), "+f"(c[3])
        : "r"(a[0]), "r"(a[1]), "r"(a[2]), "r"(a[3]), "r"(b[0]), "r"(b[1]));
}

// Swizzle: row's two 16B chunks at chunk ^ ((row>>2)&1) -> conflict-free ldmatrix.
__device__ __forceinline__ uint32_t swz(uint32_t row, uint32_t chunk16) {
    return row * 32u + (chunk16 ^ ((row & 4u) << 2));
}

// ---------------- transform kernel (no smem, fully coalesced) ----------------
// blocks [0, 2048): x NCDHW fp32 -> g_xt[b][d][h][w][cin] fp16.
//   block = (b, d, hgroup); 256 thr = 8 h x 32 w. Each thread reads 16 fp32
//   (one per cin; warp lanes span w -> 128B coalesced), packs to 2 x uint4.
// blocks [2048, 2048+54): weights OIDHW fp32 -> g_w2[tap][cout][cin].
__global__ __launch_bounds__(256) void xform_all(const float* __restrict__ x,
                                                 const float* __restrict__ w)
{
    const int t = threadIdx.x;
    if (blockIdx.x < 2048) {
        const int blk = blockIdx.x;
        const int b = blk >> 7, d = (blk >> 2) & 31, hg = blk & 3;
        const int h = hg * 8 + (t >> 5);
        const int ww = t & 31;

        const float* xp = x + ((long)(b * 16) << 15) + (d << 10) + (h << 5) + ww;
        float v[16];
        #pragma unroll
        for (int c = 0; c < 16; ++c)
            v[c] = xp[(long)c << 15];

        uint32_t r[8];
        #pragma unroll
        for (int k = 0; k < 8; ++k) {
            __half2 p = __floats2half2_rn(v[2 * k], v[2 * k + 1]);
            r[k] = *(uint32_t*)&p;
        }
        uint4* pdst = (uint4*)&g_xt[((long)(b * 32 + d) << 14) + (h << 9) + (ww << 4)];
        pdst[0] = make_uint4(r[0], r[1], r[2], r[3]);
        pdst[1] = make_uint4(r[4], r[5], r[6], r[7]);
    } else {
        const int idx = (blockIdx.x - 2048) * 256 + t;
        if (idx < 27 * 512) {
            const int tap = idx >> 9, r = idx & 511;
            const int co = r >> 4, cin = r & 15;
            g_w2[tap * 512 + r] = __float2half_rn(w[(co * 16 + cin) * 27 + tap]);
        }
    }
}

// ---------------- main kernel ----------------
// M = 512 rows per CTA; 8 warps x 4 rowtiles. 32B pitch + XOR swizzle.
// Slices staged in 3 cp.async groups; per-kd wait so kd0 compute starts after
// 55KB (not 83KB) and kd1/kd2 loads hide under compute. A fragments
// double-buffered within each kd.
#define SMEM_DYN 83136
#define SLAB0    27648
#define SLCSZ    18496

__global__ __launch_bounds__(TPB, 2) void conv_main(
    const float* __restrict__ cbias,
    const float* __restrict__ sfac,
    const float* __restrict__ bparm,
    float* __restrict__ out)
{
    extern __shared__ char sm[];
    __shared__ float e0[32], e1[32], e2n[32];

    const int d0 = blockIdx.x, b = blockIdx.y, hh = blockIdx.z;
    const int t = threadIdx.x, warp = t >> 5, lane = t & 31;
    const uint32_t smb = smem_u32(sm);
    const uint32_t ws_a = smb;
    const uint32_t sl_a = smb + SLAB0;

    const int hstart = hh * 16;
    const int rows_h = hh ? 16 : 18;
    const int chunks = rows_h * 64;

    // ---- async loads: G0 = weights + slice0; G1 = slice1; G2 = slice2
    for (int i = t; i < 1728; i += TPB)
        cp_async16(ws_a + swz((uint32_t)(i >> 1), (uint32_t)(i & 1) << 4),
                   (const char*)g_w2 + (long)i * 16);
    #pragma unroll
    for (int d = 0; d < 3; ++d) {
        const long bo = (long)((b * 32 + d0 + d) * 32 + hstart) * 1024;
        const uint32_t dh = sl_a + (uint32_t)d * SLCSZ;
        for (int i = t; i < chunks; i += TPB)
            cp_async16(dh + swz((uint32_t)(i >> 1), (uint32_t)(i & 1) << 4),
                       (const char*)g_xt + bo + (long)i * 16);
        cp_commit();
    }

    if (t < 32) {
        const float s = sfac[t];
        e0[t] = cbias[t] * s;
        e1[t] = s;
        e2n[t] = -1.4426950408889634f * bparm[t];
    }

    float acc[4][4][4];
    #pragma unroll
    for (int rt = 0; rt < 4; ++rt)
        #pragma unroll
        for (int j = 0; j < 4; ++j)
            #pragma unroll
            for (int k = 0; k < 4; ++k)
                acc[rt][j][k] = 0.0f;

    const uint32_t bn = (lane & 7) + ((lane & 16) >> 1);
    const uint32_t bc = (lane & 8) * 2;
    const uint32_t ar = (lane & 15);
    const uint32_t ac = (lane & 16);

    const uint32_t bofs  = swz(bn, bc);
    const uint32_t bofs2 = swz(bn + 16u, bc);
    const uint32_t awbase = (uint32_t)(warp * 64) + ar;

    uint32_t ah[2][4][4];       // double-buffered A fragments
    uint32_t bh[4][2];

    #pragma unroll
    for (int kd = 0; kd < 3; ++kd) {
        if (kd == 0) cp_wait<2>(); else if (kd == 1) cp_wait<1>(); else cp_wait<0>();
        __syncthreads();

        const uint32_t kd_a = sl_a + (uint32_t)kd * SLCSZ;

        // load A fragments for this kd's first tap
        {
            const uint32_t arow0 = awbase;       // kh=kw=0
            const uint32_t axor = ac ^ ((arow0 & 4u) << 2);
            #pragma unroll
            for (int rt = 0; rt < 4; ++rt)
                ldsm4(ah[(kd * 9) & 1][rt], kd_a + (arow0 + (uint32_t)rt * 16u) * 32u + axor);
        }

        #pragma unroll
        for (int t9 = 0; t9 < 9; ++t9) {
            const int tap = kd * 9 + t9;
            const int buf = tap & 1;

            // B fragments for current tap
            {
                const uint32_t base = ws_a + (uint32_t)tap * 1024u;
                uint32_t r0[4], r1[4];
                ldsm4(r0, base + bofs);
                ldsm4(r1, base + bofs2);
                bh[0][0] = r0[0]; bh[0][1] = r0[1]; bh[1][0] = r0[2]; bh[1][1] = r0[3];
                bh[2][0] = r1[0]; bh[2][1] = r1[1]; bh[3][0] = r1[2]; bh[3][1] = r1[3];
            }

            // prefetch A for next tap within this kd
            if (t9 < 8) {
                const int nr = t9 + 1;
                const int nkh = nr / 3, nkw = nr - nkh * 3;
                const uint32_t arow0 = awbase + (uint32_t)(nkh * 32 + nkw);
                const uint32_t axor = ac ^ ((arow0 & 4u) << 2);
                #pragma unroll
                for (int rt = 0; rt < 4; ++rt)
                    ldsm4(ah[buf ^ 1][rt], kd_a + (arow0 + (uint32_t)rt * 16u) * 32u + axor);
            }

            #pragma unroll
            for (int rt = 0; rt < 4; ++rt)
                #pragma unroll
                for (int j = 0; j < 4; ++j)
                    mma_f16(acc[rt][j], ah[buf][rt], bh[j]);
        }
    }

    // ---- epilogue: stage accumulators to smem (pitch 33), then coalesced store
    __syncthreads();
    float* ep = (float*)sm;
    const int g  = lane >> 2;
    const int cq = 2 * (lane & 3);
    #pragma unroll
    for (int rt = 0; rt < 4; ++rt) {
        const int R = warp * 64 + rt * 16 + g;
        #pragma unroll
        for (int j = 0; j < 4; ++j) {
            const int col = j * 8 + cq;
            ep[R * 33 + col]           = acc[rt][j][0];
            ep[R * 33 + col + 1]       = acc[rt][j][1];
            ep[(R + 8) * 33 + col]     = acc[rt][j][2];
            ep[(R + 8) * 33 + col + 1] = acc[rt][j][3];
        }
    }
    __syncthreads();

    #pragma unroll
    for (int half = 0; half < 2; ++half) {
        const int r = half * 256 + t;
        const int h = hstart + (r >> 5);
        const int w = r & 31;
        if (w < 30 && h < 30) {
            float* ob = out + (((long)b * 32 * DO_ + d0) * 30 + h) * 30 + w;
            #pragma unroll 8
            for (int co = 0; co < 32; ++co) {
                const float v = ep[r * 33 + co];
                const float y = fmaf(v, e1[co], e0[co]);
                float th; asm("tanh.approx.f32 %0, %1;" : "=f"(th) : "f"(y));
                const float z = th * e2n[co];
                float ex; asm("ex2.approx.f32 %0, %1;" : "=f"(ex) : "f"(z));
                float sg; asm("rcp.approx.f32 %0, %1;" : "=f"(sg) : "f"(1.0f + ex));
                ob[(long)co * (DO_ * 30 * 30)] = sg;
            }
        }
    }
}

// ---------------- launch ----------------
extern "C" void kernel_launch(void* const* d_in, const int* in_sizes, int n_in,
                              void* d_out, int out_size)
{
    const float* x  = (const float*)d_in[0];
    const float* w  = (const float*)d_in[1];
    const float* cb = (const float*)d_in[2];
    const float* sf = (const float*)d_in[3];
    const float* bp = (const float*)d_in[4];
    float* out      = (float*)d_out;

    cudaFuncSetAttribute(conv_main, cudaFuncAttributeMaxDynamicSharedMemorySize, SMEM_DYN);

    xform_all<<<2048 + 54, 256>>>(x, w);

    dim3 grid(DO_, 16, 2);
    conv_main<<<grid, TPB, SMEM_DYN>>>(cb, sf, bp, out);
}